// round 17
// baseline (speedup 1.0000x reference)
#include <cuda_runtime.h>
#include <cuda_bf16.h>
#include <cstdint>

#define Bc 2
#define Lc 2048
#define Hc 16
#define BHc 32
#define BM 128                 // q-rows per CTA
#define BN 64                  // s-rows per tile
#define NQT 16                 // q tiles
#define NST 32                 // s tiles
#define TILE_B 16384           // packed tile: Kf16(8K)|Vf16(8K)
#define NSTG 4                 // pipeline stages

// ---------------- device scratch ----------------
__device__ float g_part[2048 * 64];                             // per-half-chunk (32 s-rows) V column sums
__device__ unsigned char g_KV[(size_t)BHc * NST * TILE_B];      // pre-swizzled packed KV (16MB)

// ---------------- helpers ----------------
__device__ __forceinline__ uint32_t smem_u32(const void* p) {
    uint32_t a;
    asm("{ .reg .u64 t; cvta.to.shared.u64 t, %1; cvt.u32.u64 %0, t; }" : "=r"(a) : "l"(p));
    return a;
}
__device__ __forceinline__ float ex2f(float x) {
    float y; asm("ex2.approx.f32 %0, %1;" : "=f"(y) : "f"(x)); return y;
}
__device__ __forceinline__ uint32_t packf16(float lo, float hi) {
    uint32_t r;
    asm("cvt.rn.f16x2.f32 %0, %1, %2;" : "=r"(r) : "f"(hi), "f"(lo));
    return r;
}
// accumulate form: d += a*b
__device__ __forceinline__ void mma16816h(float* c, const uint32_t* a, uint32_t b0, uint32_t b1) {
    asm volatile("mma.sync.aligned.m16n8k16.row.col.f32.f16.f16.f32 "
        "{%0,%1,%2,%3}, {%4,%5,%6,%7}, {%8,%9}, {%0,%1,%2,%3};"
        : "+f"(c[0]), "+f"(c[1]), "+f"(c[2]), "+f"(c[3])
        : "r"(a[0]), "r"(a[1]), "r"(a[2]), "r"(a[3]), "r"(b0), "r"(b1));
}
// explicit-C form: d = a*b + c  (pinned zero C skips S pre-zeroing)
__device__ __forceinline__ void mma16816hc(float* d, const uint32_t* a, uint32_t b0, uint32_t b1,
                                           const float* c) {
    asm volatile("mma.sync.aligned.m16n8k16.row.col.f32.f16.f16.f32 "
        "{%0,%1,%2,%3}, {%4,%5,%6,%7}, {%8,%9}, {%10,%11,%12,%13};"
        : "=f"(d[0]), "=f"(d[1]), "=f"(d[2]), "=f"(d[3])
        : "r"(a[0]), "r"(a[1]), "r"(a[2]), "r"(a[3]), "r"(b0), "r"(b1),
          "f"(c[0]), "f"(c[1]), "f"(c[2]), "f"(c[3]));
}
__device__ __forceinline__ void ldsm4(uint32_t addr, uint32_t* r) {
    asm volatile("ldmatrix.sync.aligned.m8n8.x4.shared.b16 {%0,%1,%2,%3}, [%4];"
        : "=r"(r[0]), "=r"(r[1]), "=r"(r[2]), "=r"(r[3]) : "r"(addr));
}
__device__ __forceinline__ void ldsm4t(uint32_t addr, uint32_t* r) {
    asm volatile("ldmatrix.sync.aligned.m8n8.x4.trans.shared.b16 {%0,%1,%2,%3}, [%4];"
        : "=r"(r[0]), "=r"(r[1]), "=r"(r[2]), "=r"(r[3]) : "r"(addr));
}
__device__ __forceinline__ void bulk_ld(uint32_t dst, const void* src, uint32_t bytes, uint32_t mbar) {
    asm volatile("cp.async.bulk.shared::cluster.global.mbarrier::complete_tx::bytes [%0], [%1], %2, [%3];"
        :: "r"(dst), "l"(src), "r"(bytes), "r"(mbar) : "memory");
}
#define MBAR_INIT(addr, cnt) \
    asm volatile("mbarrier.init.shared.b64 [%0], %1;" :: "r"((uint32_t)(addr)), "r"((uint32_t)(cnt)) : "memory")
#define MBAR_EXPECT_TX(addr, tx) \
    asm volatile("mbarrier.arrive.expect_tx.shared.b64 _, [%0], %1;" :: "r"((uint32_t)(addr)), "r"((uint32_t)(tx)) : "memory")
#define MBAR_ARRIVE(addr) \
    asm volatile("mbarrier.arrive.shared.b64 _, [%0];" :: "r"((uint32_t)(addr)) : "memory")
#define MBAR_WAIT(addr, par) do { \
    uint32_t _m = (uint32_t)(addr); uint32_t _p = (uint32_t)(par); uint32_t _d; \
    asm volatile("{ .reg .pred p; mbarrier.try_wait.parity.acquire.cta.shared::cta.b64 p, [%1], %2; selp.b32 %0,1,0,p; }" \
        : "=r"(_d) : "r"(_m), "r"(_p) : "memory"); \
    if (!_d) { \
        asm volatile("{ .reg .pred P1; WL_%=: mbarrier.try_wait.parity.acquire.cta.shared::cta.b64 P1, [%0], %1, 0x989680; @P1 bra.uni WD_%=; bra.uni WL_%=; WD_%=: }" \
            :: "r"(_m), "r"(_p) : "memory"); \
    } } while (0)

// ---------------- preprocessing: convert + per-half-chunk V sums, MLP-8 ----------------
// 1024 blocks x 256 threads; thread owns a quarter-row (16 floats) of K and V.
// One block covers 64 s-rows of one bh -> writes 2 g_part half-chunk entries.
__global__ void convert_kv(const float* __restrict__ K, const float* __restrict__ V) {
    __shared__ float vsum[64 * 64];                  // [s_local 64][d 64]
    uint32_t n = blockIdx.x * 256 + threadIdx.x;     // 262144 threads
    int q  = n & 3;                                  // quarter-row: 16 floats
    int s  = (n >> 2) & 2047;
    int bh = n >> 13;
    int b = bh >> 4, h = bh & 15;
    int t = s >> 6, sr = s & 63;

    const float* kp = K + (((size_t)b * Lc + s) * Hc + h) * 64 + q * 16;
    const float* vp = V + (((size_t)b * Lc + s) * Hc + h) * 64 + q * 16;

    // 8 independent 16B loads in flight
    float4 k0 = *(const float4*)(kp +  0), k1 = *(const float4*)(kp +  4);
    float4 k2 = *(const float4*)(kp +  8), k3 = *(const float4*)(kp + 12);
    float4 v0 = *(const float4*)(vp +  0), v1 = *(const float4*)(vp +  4);
    float4 v2 = *(const float4*)(vp +  8), v3 = *(const float4*)(vp + 12);

    uint4 kh0, kh1, vh0, vh1;
    kh0.x = packf16(k0.x, k0.y); kh0.y = packf16(k0.z, k0.w);
    kh0.z = packf16(k1.x, k1.y); kh0.w = packf16(k1.z, k1.w);
    kh1.x = packf16(k2.x, k2.y); kh1.y = packf16(k2.z, k2.w);
    kh1.z = packf16(k3.x, k3.y); kh1.w = packf16(k3.z, k3.w);
    vh0.x = packf16(v0.x, v0.y); vh0.y = packf16(v0.z, v0.w);
    vh0.z = packf16(v1.x, v1.y); vh0.w = packf16(v1.z, v1.w);
    vh1.x = packf16(v2.x, v2.y); vh1.y = packf16(v2.z, v2.w);
    vh1.z = packf16(v3.x, v3.y); vh1.w = packf16(v3.z, v3.w);

    size_t tb = ((size_t)(bh * NST + t)) * TILE_B;
    uint32_t b0 = (uint32_t)sr * 128 + (uint32_t)q * 32;
    uint32_t b1 = b0 + 16;
    uint32_t sw = ((uint32_t)sr & 7) << 4;
    uint32_t r0 = (b0 & ~127u) | ((b0 & 127u) ^ sw);
    uint32_t r1 = (b1 & ~127u) | ((b1 & 127u) ^ sw);
    *(uint4*)(g_KV + tb +    0 + r0) = kh0;
    *(uint4*)(g_KV + tb +    0 + r1) = kh1;
    *(uint4*)(g_KV + tb + 8192 + r0) = vh0;
    *(uint4*)(g_KV + tb + 8192 + r1) = vh1;

    // stage V for column sums: row sl (0..63), cols q*16..q*16+15
    int sl = (threadIdx.x >> 2);                     // 64 s-rows per block
    float* vs = &vsum[sl * 64 + q * 16];
    *(float4*)&vs[0]  = v0; *(float4*)&vs[4]  = v1;
    *(float4*)&vs[8]  = v2; *(float4*)&vs[12] = v3;
    __syncthreads();
    if (threadIdx.x < 128) {
        int hcl = threadIdx.x >> 6;                  // local half-chunk 0/1
        int d = threadIdx.x & 63;
        float acc = 0.f;
        #pragma unroll 8
        for (int r = 0; r < 32; ++r) acc += vsum[(hcl * 32 + r) * 64 + d];
        g_part[(uint32_t)(blockIdx.x * 2 + hcl) * 64 + d] = acc;
    }
}

// ---------------- main attention kernel (R16 body — frozen best) ----------------
#define QSCALE 0.18033688011112042f   // 0.125 * log2(e)
#define ONES2  0x3C003C00u            // two fp16 1.0
#define SM_FULL0  (NSTG * TILE_B)         // full[4]: tx barriers
#define SM_EMPTY0 (NSTG * TILE_B + 32)    // empty[4]: 8 warp-arrival barriers
#define SM_TOTAL  (NSTG * TILE_B + 128)   // 65664 -> 2 CTAs/SM

extern __shared__ __align__(1024) char dynsm[];

template <bool MASKED>
__device__ __forceinline__ void tile_body(
    int t, int st, int rpar, int tmax_glob, uint32_t sm, const unsigned char* kvbase,
    const uint32_t Qh[4][4], const uint32_t koff[4], const uint32_t voff[4],
    const float zc[4],
    float Oa[8][4], float Dden[4],
    int tid, int lane, int rowglob)
{
    MBAR_WAIT(sm + SM_FULL0 + st * 8, rpar);

    const uint32_t stg = sm + (uint32_t)st * TILE_B;
    const uint32_t k_b = stg, v_b = stg + 8192;

    // ---- S = Q Kt (single fp16); kc=0 uses explicit zero-C ----
    float S[8][4];
    #pragma unroll
    for (int kc = 0; kc < 4; ++kc) {
        #pragma unroll
        for (int nbp = 0; nbp < 4; ++nbp) {
            uint32_t kb[4];
            ldsm4(k_b + koff[kc] + (uint32_t)nbp * 2048, kb);
            if (kc == 0) {
                mma16816hc(S[2*nbp],   Qh[0], kb[0], kb[1], zc);
                mma16816hc(S[2*nbp+1], Qh[0], kb[2], kb[3], zc);
            } else {
                mma16816h(S[2*nbp],   Qh[kc], kb[0], kb[1]);
                mma16816h(S[2*nbp+1], Qh[kc], kb[2], kb[3]);
            }
        }
    }

    // ---- prefetch V for kcs=0 (overlaps the exp MUFU stretch) ----
    uint32_t vbuf[2][4][4];
    #pragma unroll
    for (int nbp = 0; nbp < 4; ++nbp)
        ldsm4t(v_b + voff[nbp], vbuf[0][nbp]);

    // ---- exp; masked (future) slots contribute exp(0)=1 (reference semantics) ----
    const int quad = lane & 3;
    const int lim0 = MASKED ? (rowglob - (t << 6)) : 0;
    const int lim1 = lim0 + 8;
    uint32_t Ph[4][4];
    #pragma unroll
    for (int nb = 0; nb < 8; ++nb) {
        float p0, p1, p2, p3;
        if (MASKED) {
            int s0 = nb * 8 + quad * 2;
            p0 = (s0     <= lim0) ? ex2f(S[nb][0]) : 1.f;
            p1 = (s0 + 1 <= lim0) ? ex2f(S[nb][1]) : 1.f;
            p2 = (s0     <= lim1) ? ex2f(S[nb][2]) : 1.f;
            p3 = (s0 + 1 <= lim1) ? ex2f(S[nb][3]) : 1.f;
        } else {
            p0 = ex2f(S[nb][0]);
            p1 = ex2f(S[nb][1]);
            p2 = ex2f(S[nb][2]);
            p3 = ex2f(S[nb][3]);
        }
        Ph[nb >> 1][(nb & 1) * 2]     = packf16(p0, p1);
        Ph[nb >> 1][(nb & 1) * 2 + 1] = packf16(p2, p3);
    }

    // ---- O += P V, den += P*ones; den MMA fills tensor pipe during V-ldsm windows ----
    #pragma unroll
    for (int kcs = 0; kcs < 4; ++kcs) {
        if (kcs < 3) {
            #pragma unroll
            for (int nbp = 0; nbp < 4; ++nbp)
                ldsm4t(v_b + voff[nbp] + (uint32_t)(kcs + 1) * 2048, vbuf[(kcs + 1) & 1][nbp]);
        }
        mma16816h(Dden, Ph[kcs], ONES2, ONES2);
        #pragma unroll
        for (int nbp = 0; nbp < 4; ++nbp) {
            const uint32_t* vb = vbuf[kcs & 1][nbp];
            mma16816h(Oa[2*nbp],   Ph[kcs], vb[0], vb[1]);
            mma16816h(Oa[2*nbp+1], Ph[kcs], vb[2], vb[3]);
        }
    }

    if (lane == 0) MBAR_ARRIVE(sm + SM_EMPTY0 + st * 8);

    if (tid == 0 && t + NSTG <= tmax_glob) {
        MBAR_WAIT(sm + SM_EMPTY0 + st * 8, rpar);
        MBAR_EXPECT_TX(sm + SM_FULL0 + st * 8, TILE_B);
        bulk_ld(stg, kvbase + (size_t)(t + NSTG) * TILE_B, TILE_B, sm + SM_FULL0 + st * 8);
    }
}

__global__ void __launch_bounds__(256, 2) attn_mma(const float* __restrict__ Q,
                                                   float* __restrict__ O) {
    const uint32_t sm = smem_u32(dynsm);
    const int tid = threadIdx.x;
    const int w = tid >> 5, lane = tid & 31;
    const int g = lane >> 2, quad = lane & 3;
    const int bh = blockIdx.y, b = bh >> 4, h = bh & 15;
    const int mtile = (NQT - 1) - (int)blockIdx.x;   // heavy q-tiles first
    const int tmax_glob = 2 * mtile + 1;
    const int nproc = 2 * mtile + 2 - (w < 4 ? 1 : 0);   // tiles processed; last one MASKED

    if (tid == 0) {
        #pragma unroll
        for (int s = 0; s < NSTG; ++s) {
            MBAR_INIT(sm + SM_FULL0 + s * 8, 1);
            MBAR_INIT(sm + SM_EMPTY0 + s * 8, 8);
        }
    }
    __syncthreads();

    // prologue FIRST: TMA fills overlap the Q global loads below
    const unsigned char* kvbase = g_KV + (size_t)bh * NST * TILE_B;
    if (tid == 0) {
        #pragma unroll
        for (int s = 0; s < NSTG; ++s) {
            if (s <= tmax_glob) {
                MBAR_EXPECT_TX(sm + SM_FULL0 + s * 8, TILE_B);
                bulk_ld(sm + s * TILE_B, kvbase + (size_t)s * TILE_B, TILE_B,
                        sm + SM_FULL0 + s * 8);
            }
        }
    }

    // per-lane ldmatrix geometry, hoisted to offset tables
    const int ks_row = (lane & 7) + ((lane >> 4) << 3);
    const uint32_t k_col = ((uint32_t)((lane >> 3) & 1)) * 16;
    const int vs_row = (lane & 7) + (((lane >> 3) & 1) << 3);
    const uint32_t v_col = ((uint32_t)(lane >> 4)) << 4;
    const uint32_t xo = ((uint32_t)(lane & 7)) << 4;
    uint32_t koff[4], voff[4];
    #pragma unroll
    for (int kc = 0; kc < 4; ++kc)
        koff[kc] = (uint32_t)ks_row * 128 + (((uint32_t)kc * 32 + k_col) ^ xo);
    #pragma unroll
    for (int nbp = 0; nbp < 4; ++nbp)
        voff[nbp] = (uint32_t)vs_row * 128 + (((uint32_t)nbp * 32 + v_col) ^ xo);

    // ---- Q fragments (single fp16, scale folded in) ----
    uint32_t Qh[4][4];
    {
        const float* qb = Q + (((size_t)b * Lc + (size_t)mtile * BM + w * 16) * Hc + h) * 64;
        #pragma unroll
        for (int kc = 0; kc < 4; ++kc) {
            int e0 = kc * 16 + quad * 2;
            float2 v00 = *(const float2*)(qb + (size_t)g * 1024 + e0);
            float2 v10 = *(const float2*)(qb + (size_t)(g + 8) * 1024 + e0);
            float2 v01 = *(const float2*)(qb + (size_t)g * 1024 + e0 + 8);
            float2 v11 = *(const float2*)(qb + (size_t)(g + 8) * 1024 + e0 + 8);
            Qh[kc][0] = packf16(v00.x * QSCALE, v00.y * QSCALE);
            Qh[kc][1] = packf16(v10.x * QSCALE, v10.y * QSCALE);
            Qh[kc][2] = packf16(v01.x * QSCALE, v01.y * QSCALE);
            Qh[kc][3] = packf16(v11.x * QSCALE, v11.y * QSCALE);
        }
    }

    float Oa[8][4];
    #pragma unroll
    for (int i = 0; i < 8; ++i)
        #pragma unroll
        for (int j = 0; j < 4; ++j) Oa[i][j] = 0.f;
    float Dden[4] = {0.f, 0.f, 0.f, 0.f};
    const float zc[4] = {0.f, 0.f, 0.f, 0.f};

    const int rowA = w * 16 + g;
    const int rowglob = mtile * BM + rowA;

    int t = 0, st = 0, rp = 0;
    #pragma unroll 4
    for (; t < nproc - 1; ++t) {
        tile_body<false>(t, st, rp, tmax_glob, sm, kvbase, Qh, koff, voff, zc,
                         Oa, Dden, tid, lane, rowglob);
        if (++st == NSTG) { st = 0; rp ^= 1; }
    }
    tile_body<true>(t, st, rp, tmax_glob, sm, kvbase, Qh, koff, voff, zc,
                    Oa, Dden, tid, lane, rowglob);

    // ---- epilogue: direct suffix-sum of per-half-chunk V sums (validated R15) ----
    float sfx2[8][2];
    #pragma unroll
    for (int nb = 0; nb < 8; ++nb) { sfx2[nb][0] = 0.f; sfx2[nb][1] = 0.f; }
    {
        const int d0base = quad * 2;
        #pragma unroll 1
        for (int hc = 2 * nproc; hc < 64; ++hc) {
            const float* pp = &g_part[(uint32_t)((bh << 6) + hc) << 6];
            #pragma unroll
            for (int nb = 0; nb < 8; ++nb) {
                float2 s2 = *(const float2*)(pp + nb * 8 + d0base);
                sfx2[nb][0] += s2.x;
                sfx2[nb][1] += s2.y;
            }
        }
    }

    const float corr = (float)(Lc - BN * nproc);   // masked slots beyond processed tiles
    const float inv0 = 1.f / (Dden[0] + corr);
    const float inv1 = 1.f / (Dden[2] + corr);

    const int r0g = rowglob;
    const int r1g = r0g + 8;
    const size_t ob0 = (((size_t)b * Lc + r0g) * Hc + h) * 64;
    const size_t ob1 = (((size_t)b * Lc + r1g) * Hc + h) * 64;

    #pragma unroll
    for (int nb = 0; nb < 8; ++nb) {
        int d0 = nb * 8 + quad * 2;
        float2 o0 = make_float2((Oa[nb][0] + sfx2[nb][0]) * inv0, (Oa[nb][1] + sfx2[nb][1]) * inv0);
        float2 o1 = make_float2((Oa[nb][2] + sfx2[nb][0]) * inv1, (Oa[nb][3] + sfx2[nb][1]) * inv1);
        *(float2*)&O[ob0 + d0] = o0;
        *(float2*)&O[ob1 + d0] = o1;
    }
}

// ---------------- launch ----------------
extern "C" void kernel_launch(void* const* d_in, const int* in_sizes, int n_in,
                              void* d_out, int out_size) {
    const float* Q = (const float*)d_in[0];
    const float* K = (const float*)d_in[1];
    const float* V = (const float*)d_in[2];
    float* O = (float*)d_out;

    convert_kv<<<1024, 256>>>(K, V);

    cudaFuncSetAttribute(attn_mma, cudaFuncAttributeMaxDynamicSharedMemorySize, SM_TOTAL);
    attn_mma<<<dim3(NQT, BHc), 256, SM_TOTAL>>>(Q, O);
}